// round 9
// baseline (speedup 1.0000x reference)
#include <cuda_runtime.h>
#include <cuda_fp16.h>
#include <math.h>

#define NG 131072
#define NM 40962
#define NE 524288
#define DD 128

#define BLK_R 64
#define KC 32
#define NTH 256

#define AP 40     // A pitch (fp32 elems)
#define BPh 40    // B pitch (half elems) -> 80B rows
#define HPh 136   // H pitch (half elems) -> 272B rows
#define YP 132    // Y pitch (fp32 elems)

#define ASZ 10240            // 64*40*4 per A stage
#define BSZ 10240            // 128*40*2 per B stage
#define OFF_AS 0             // 3 A stages: 0..30720
#define OFF_BS 30720         // 3 B stages: 30720..61440
#define OFF_HS 0             // H fp16: 64*136*2 = 17408 (overlaps dead A)
#define OFF_Y  0             // Y fp32: 64*132*4 = 33792 (overlaps A + dead B head)
#define OFF_IS 61440
#define OFF_ID 61696
#define SMEM_BYTES 61952

__device__ float g_agg[(size_t)NM * DD];
// fp16 transposed weights: eW0t(128x384), eW1t, sW0t, sW1t, dW0t(128x256), dW1t
__device__ __half g_wh[147456];

__global__ void zero_agg_kernel() {
    size_t n = (size_t)NM * DD / 4;
    float4 z = make_float4(0.f, 0.f, 0.f, 0.f);
    float4* p = (float4*)g_agg;
    for (size_t i = blockIdx.x * (size_t)blockDim.x + threadIdx.x; i < n;
         i += (size_t)gridDim.x * blockDim.x) p[i] = z;
}

__global__ void prep_weights(const float* __restrict__ eW0, const float* __restrict__ eW1,
                             const float* __restrict__ sW0, const float* __restrict__ sW1,
                             const float* __restrict__ dW0, const float* __restrict__ dW1) {
    int i = blockIdx.x * blockDim.x + threadIdx.x;
    if (i >= 147456) return;
    float v;
    if (i < 49152)       { int j = i;          v = eW0[(j % 384) * 128 + (j / 384)]; }
    else if (i < 65536)  { int j = i - 49152;  v = eW1[(j % 128) * 128 + (j / 128)]; }
    else if (i < 81920)  { int j = i - 65536;  v = sW0[(j % 128) * 128 + (j / 128)]; }
    else if (i < 98304)  { int j = i - 81920;  v = sW1[(j % 128) * 128 + (j / 128)]; }
    else if (i < 131072) { int j = i - 98304;  v = dW0[(j % 256) * 128 + (j / 256)]; }
    else                 { int j = i - 131072; v = dW1[(j % 128) * 128 + (j / 128)]; }
    g_wh[i] = __float2half_rn(v);
}

__device__ __forceinline__ void cp16(unsigned saddr, const void* g, bool pred) {
    int sz = pred ? 16 : 0;
    asm volatile("cp.async.cg.shared.global [%0], [%1], 16, %2;\n"
                 :: "r"(saddr), "l"(g), "r"(sz));
}
#define CP_COMMIT asm volatile("cp.async.commit_group;\n")
template <int N>
__device__ __forceinline__ void cp_wait() {
    asm volatile("cp.async.wait_group %0;\n" :: "n"(N));
}

__device__ __forceinline__ unsigned packh2(float lo, float hi) {
    unsigned r;
    asm("cvt.rn.f16x2.f32 %0, %1, %2;" : "=r"(r) : "f"(hi), "f"(lo));
    return r;
}

__device__ __forceinline__ void ldsm4(unsigned& r0, unsigned& r1, unsigned& r2, unsigned& r3,
                                      unsigned addr) {
    asm volatile("ldmatrix.sync.aligned.m8n8.x4.shared.b16 {%0,%1,%2,%3}, [%4];"
                 : "=r"(r0), "=r"(r1), "=r"(r2), "=r"(r3) : "r"(addr));
}

__device__ __forceinline__ void mma16(float* d, const unsigned* a, unsigned b0, unsigned b1) {
    asm volatile(
        "mma.sync.aligned.m16n8k16.row.col.f32.f16.f16.f32 "
        "{%0,%1,%2,%3}, {%4,%5,%6,%7}, {%8,%9}, {%0,%1,%2,%3};\n"
        : "+f"(d[0]), "+f"(d[1]), "+f"(d[2]), "+f"(d[3])
        : "r"(a[0]), "r"(a[1]), "r"(a[2]), "r"(a[3]), "r"(b0), "r"(b1));
}

// MODE 0: edge MLP  (concat(efeat, grid[src], mesh[dst]) -> red.v4 scatter into agg[dst])
// MODE 1: plain MLP (Xa -> resid + out)
// MODE 2: dst MLP   (concat(agg, mesh) -> resid + out)
template <int K1, int MODE>
__global__ __launch_bounds__(NTH, 3)
void mlp_tc(const float* __restrict__ Xa,
            const float* __restrict__ Xb,
            const float* __restrict__ Xc,
            const int* __restrict__ src_idx,
            const int* __restrict__ dst_idx,
            const __half* __restrict__ W0t, const float* __restrict__ b0v,
            const __half* __restrict__ W1t, const float* __restrict__ b1v,
            const float* __restrict__ gamma, const float* __restrict__ beta,
            const float* __restrict__ resid,
            float* __restrict__ out,
            float* __restrict__ agg,
            int R)
{
    extern __shared__ unsigned char smem[];
    unsigned* Hu = (unsigned*)(smem + OFF_HS);
    float*    Ys = (float*)(smem + OFF_Y);
    int*      Is = (int*)(smem + OFF_IS);
    int*      Id = (int*)(smem + OFF_ID);
    const unsigned sbase = (unsigned)__cvta_generic_to_shared(smem);

    const int t   = threadIdx.x;
    const int wid = t >> 5;
    const int l   = t & 31;
    const int lr  = l >> 2;
    const int lc  = l & 3;
    const int warpM = wid >> 1;          // 0..3 -> 16 rows each
    const int warpN = wid & 1;           // 0..1 -> 64 cols each
    const int wr0 = warpM * 16;
    const int wc0 = warpN * 64;
    const int rowBase = blockIdx.x * BLK_R;

    // ldmatrix lane-address bases
    const int mi = l >> 3;
    const int rr = l & 7;
    const unsigned baseB = sbase + OFF_BS
        + 80u * (unsigned)(wc0 + 8 * (mi >> 1) + rr) + 16u * (unsigned)(mi & 1);
    const unsigned baseH = sbase + OFF_HS
        + 272u * (unsigned)(wr0 + 8 * (mi & 1) + rr) + 16u * (unsigned)(mi >> 1);

    if (MODE == 0) {
        if (t < 64) {
            Is[t] = src_idx[rowBase + t];
            Id[t] = dst_idx[rowBase + t];
        }
        __syncthreads();
    }

    // ---- async tile loaders ----
    auto load_a = [&](int k0, int buf) {
#pragma unroll
        for (int j = 0; j < 2; ++j) {
            int idx = t + j * 256;
            int r   = idx >> 3;          // 0..63
            int c4  = (idx & 7) * 4;     // 0..28
            int rg  = rowBase + r;
            bool pred = (MODE == 0) ? true : (rg < R);
            int rgc = pred ? rg : (R - 1);
            const float* src;
            if (MODE == 0) {
                int seg = k0 >> 7;
                int cc  = (k0 & 127) + c4;
                src = (seg == 0) ? Xa + (size_t)rg * 128 + cc
                    : (seg == 1) ? Xb + (size_t)Is[r] * 128 + cc
                                 : Xc + (size_t)Id[r] * 128 + cc;
            } else if (MODE == 1) {
                src = Xa + (size_t)rgc * 128 + k0 + c4;
            } else {
                int seg = k0 >> 7;
                int cc  = (k0 & 127) + c4;
                src = (seg == 0) ? Xa + (size_t)rgc * 128 + cc
                                 : Xb + (size_t)rgc * 128 + cc;
            }
            cp16(sbase + OFF_AS + (unsigned)buf * ASZ + (unsigned)(r * AP + c4) * 4u, src, pred);
        }
    };
    auto load_b = [&](const __half* Wt, int KS, int k0, int buf) {
#pragma unroll
        for (int j = 0; j < 2; ++j) {
            int idx = t + j * 256;
            int n = idx >> 2;
            int ch = idx & 3;
            cp16(sbase + OFF_BS + (unsigned)buf * BSZ + (unsigned)(n * BPh * 2 + ch * 16),
                 Wt + (size_t)n * KS + k0 + ch * 8, true);
        }
    };

    constexpr int NCH1 = K1 / KC;
    constexpr int NCH2 = 4;

    // ---------------- GEMM1: acc = f16(X) @ W0t ----------------
    float acc[8][4];
#pragma unroll
    for (int n = 0; n < 8; ++n)
#pragma unroll
        for (int j = 0; j < 4; ++j) acc[n][j] = 0.0f;

    load_a(0, 0); load_b(W0t, K1, 0, 0); CP_COMMIT;
    load_a(KC, 1); load_b(W0t, K1, KC, 1); CP_COMMIT;

#pragma unroll 1
    for (int kb = 0; kb < NCH1; ++kb) {
        cp_wait<1>();
        __syncthreads();
        int p = kb + 2;
        if (p < NCH1) {
            load_a(p * KC, p % 3); load_b(W0t, K1, p * KC, p % 3); CP_COMMIT;
        } else if (p - NCH1 < NCH2) {
            load_b(W1t, 128, (p - NCH1) * KC, p % 3); CP_COMMIT;
        }
        const int bufc = kb % 3;
        const float* Af = (const float*)(smem + OFF_AS + bufc * ASZ);
        const unsigned bB = baseB + (unsigned)bufc * BSZ;
#pragma unroll
        for (int ks = 0; ks < 2; ++ks) {
            unsigned bfr[8][2];
#pragma unroll
            for (int g = 0; g < 4; ++g)
                ldsm4(bfr[2 * g][0], bfr[2 * g][1], bfr[2 * g + 1][0], bfr[2 * g + 1][1],
                      bB + 1280u * g + 32u * ks);
            unsigned a[4];
            int c0 = ks * 16 + 2 * lc;
            {
                int r = wr0 + lr;
                float2 f0 = *(const float2*)&Af[r * AP + c0];
                float2 f1 = *(const float2*)&Af[(r + 8) * AP + c0];
                float2 f2 = *(const float2*)&Af[r * AP + c0 + 8];
                float2 f3 = *(const float2*)&Af[(r + 8) * AP + c0 + 8];
                a[0] = packh2(f0.x, f0.y);
                a[1] = packh2(f1.x, f1.y);
                a[2] = packh2(f2.x, f2.y);
                a[3] = packh2(f3.x, f3.y);
            }
#pragma unroll
            for (int nt = 0; nt < 8; ++nt)
                mma16(acc[nt], a, bfr[nt][0], bfr[nt][1]);
        }
    }
    __syncthreads();   // all warps done with A stages before H overwrites them

    // bias + SiLU -> H (fp16, overlaps dead A region)
#pragma unroll
    for (int nt = 0; nt < 8; ++nt) {
        int c  = wc0 + nt * 8 + 2 * lc;
        float2 bb = *(const float2*)&b0v[c];
        int r1 = wr0 + lr;
        int r2 = r1 + 8;
        float x0 = acc[nt][0] + bb.x;
        float x1 = acc[nt][1] + bb.y;
        float x2 = acc[nt][2] + bb.x;
        float x3 = acc[nt][3] + bb.y;
        float s0 = x0 / (1.0f + __expf(-x0));
        float s1 = x1 / (1.0f + __expf(-x1));
        float s2 = x2 / (1.0f + __expf(-x2));
        float s3 = x3 / (1.0f + __expf(-x3));
        Hu[(r1 * HPh + c) >> 1] = packh2(s0, s1);
        Hu[(r2 * HPh + c) >> 1] = packh2(s2, s3);
    }
    __syncthreads();

    // ---------------- GEMM2: y = H @ W1t ----------------
    float acc2[8][4];
#pragma unroll
    for (int n = 0; n < 8; ++n)
#pragma unroll
        for (int j = 0; j < 4; ++j) acc2[n][j] = 0.0f;

#pragma unroll 1
    for (int j = 0; j < NCH2; ++j) {
        cp_wait<1>();
        __syncthreads();
        if (j + 2 < NCH2) { load_b(W1t, 128, (j + 2) * KC, (NCH1 + j + 2) % 3); CP_COMMIT; }
        const int bufc = (NCH1 + j) % 3;
        const unsigned bB = baseB + (unsigned)bufc * BSZ;
#pragma unroll
        for (int ks = 0; ks < 2; ++ks) {
            unsigned bfr[8][2];
#pragma unroll
            for (int g = 0; g < 4; ++g)
                ldsm4(bfr[2 * g][0], bfr[2 * g][1], bfr[2 * g + 1][0], bfr[2 * g + 1][1],
                      bB + 1280u * g + 32u * ks);
            unsigned a[4];
            ldsm4(a[0], a[1], a[2], a[3], baseH + 64u * j + 32u * ks);
#pragma unroll
            for (int nt = 0; nt < 8; ++nt)
                mma16(acc2[nt], a, bfr[nt][0], bfr[nt][1]);
        }
    }
    __syncthreads();   // all compute done before Y overwrites A/B regions

    // y = acc2 + b1 -> Y (fp32)
#pragma unroll
    for (int nt = 0; nt < 8; ++nt) {
        int c  = wc0 + nt * 8 + 2 * lc;
        float2 bb = *(const float2*)&b1v[c];
        int r1 = wr0 + lr;
        int r2 = r1 + 8;
        float2 y1; y1.x = acc2[nt][0] + bb.x; y1.y = acc2[nt][1] + bb.y;
        float2 y2; y2.x = acc2[nt][2] + bb.x; y2.y = acc2[nt][3] + bb.y;
        *(float2*)&Ys[r1 * YP + c] = y1;
        *(float2*)&Ys[r2 * YP + c] = y2;
    }
    __syncthreads();

    // ---------------- LayerNorm + epilogue (warp w owns rows w*8..w*8+7) ----------------
    float4 gg = *(const float4*)&gamma[l * 4];
    float4 bt = *(const float4*)&beta[l * 4];

#pragma unroll 4
    for (int i = 0; i < 8; ++i) {
        int r  = wid * 8 + i;
        int rg = rowBase + r;
        float4 v = *(const float4*)&Ys[r * YP + l * 4];
        float s  = v.x + v.y + v.z + v.w;
        float ss = v.x * v.x + v.y * v.y + v.z * v.z + v.w * v.w;
#pragma unroll
        for (int off = 16; off > 0; off >>= 1) {
            s  += __shfl_xor_sync(0xFFFFFFFFu, s,  off);
            ss += __shfl_xor_sync(0xFFFFFFFFu, ss, off);
        }
        float mean = s * (1.0f / DD);
        float var  = ss * (1.0f / DD) - mean * mean;
        float rstd = rsqrtf(var + 1e-5f);

        float4 o;
        o.x = (v.x - mean) * rstd * gg.x + bt.x;
        o.y = (v.y - mean) * rstd * gg.y + bt.y;
        o.z = (v.z - mean) * rstd * gg.z + bt.z;
        o.w = (v.w - mean) * rstd * gg.w + bt.w;

        if (MODE == 0) {
            float* p = &agg[(size_t)Id[r] * DD + l * 4];
            asm volatile("red.global.add.v4.f32 [%0], {%1,%2,%3,%4};"
                         :: "l"(p), "f"(o.x), "f"(o.y), "f"(o.z), "f"(o.w)
                         : "memory");
        } else {
            if (rg < R) {
                float4 rv = *(const float4*)&resid[(size_t)rg * DD + l * 4];
                o.x += rv.x; o.y += rv.y; o.z += rv.z; o.w += rv.w;
                *(float4*)&out[(size_t)rg * DD + l * 4] = o;
            }
        }
    }
}

extern "C" void kernel_launch(void* const* d_in, const int* in_sizes, int n_in,
                              void* d_out, int out_size)
{
    const float* efeat   = (const float*)d_in[0];
    const float* grid    = (const float*)d_in[1];
    const float* mesh    = (const float*)d_in[2];
    const int*   src_idx = (const int*)d_in[3];
    const int*   dst_idx = (const int*)d_in[4];
    const float* eW0 = (const float*)d_in[5];
    const float* eb0 = (const float*)d_in[6];
    const float* eW1 = (const float*)d_in[7];
    const float* eb1 = (const float*)d_in[8];
    const float* eg  = (const float*)d_in[9];
    const float* ebt = (const float*)d_in[10];
    const float* sW0 = (const float*)d_in[11];
    const float* sb0 = (const float*)d_in[12];
    const float* sW1 = (const float*)d_in[13];
    const float* sb1 = (const float*)d_in[14];
    const float* sg  = (const float*)d_in[15];
    const float* sbt = (const float*)d_in[16];
    const float* dW0 = (const float*)d_in[17];
    const float* db0 = (const float*)d_in[18];
    const float* dW1 = (const float*)d_in[19];
    const float* db1 = (const float*)d_in[20];
    const float* dg  = (const float*)d_in[21];
    const float* dbt = (const float*)d_in[22];

    float* out_grid = (float*)d_out;
    float* out_mesh = (float*)d_out + (size_t)NG * DD;

    float* agg_ptr = nullptr;
    cudaGetSymbolAddress((void**)&agg_ptr, g_agg);
    __half* wh_ptr = nullptr;
    cudaGetSymbolAddress((void**)&wh_ptr, g_wh);

    static bool attr_done = false;
    if (!attr_done) {
        cudaFuncSetAttribute(mlp_tc<384, 0>, cudaFuncAttributeMaxDynamicSharedMemorySize, SMEM_BYTES);
        cudaFuncSetAttribute(mlp_tc<128, 1>, cudaFuncAttributeMaxDynamicSharedMemorySize, SMEM_BYTES);
        cudaFuncSetAttribute(mlp_tc<256, 2>, cudaFuncAttributeMaxDynamicSharedMemorySize, SMEM_BYTES);
        attr_done = true;
    }

    prep_weights<<<576, 256>>>(eW0, eW1, sW0, sW1, dW0, dW1);
    zero_agg_kernel<<<512, 256>>>();

    const __half* weW0t = wh_ptr;
    const __half* weW1t = wh_ptr + 49152;
    const __half* wsW0t = wh_ptr + 65536;
    const __half* wsW1t = wh_ptr + 81920;
    const __half* wdW0t = wh_ptr + 98304;
    const __half* wdW1t = wh_ptr + 131072;

    mlp_tc<384, 0><<<NE / BLK_R, NTH, SMEM_BYTES>>>(
        efeat, grid, mesh, src_idx, dst_idx,
        weW0t, eb0, weW1t, eb1, eg, ebt,
        nullptr, nullptr, agg_ptr, NE);

    mlp_tc<128, 1><<<NG / BLK_R, NTH, SMEM_BYTES>>>(
        grid, nullptr, nullptr, nullptr, nullptr,
        wsW0t, sb0, wsW1t, sb1, sg, sbt,
        grid, out_grid, nullptr, NG);

    mlp_tc<256, 2><<<(NM + BLK_R - 1) / BLK_R, NTH, SMEM_BYTES>>>(
        agg_ptr, mesh, nullptr, nullptr, nullptr,
        wdW0t, db0, wdW1t, db1, dg, dbt,
        mesh, out_mesh, nullptr, NM);
}

// round 12
// speedup vs baseline: 1.0859x; 1.0859x over previous
#include <cuda_runtime.h>
#include <cuda_fp16.h>
#include <math.h>

#define NG 131072
#define NM 40962
#define NE 524288
#define DD 128

#define BLK_R 64
#define KC 32
#define NTH 256

#define AP 40     // A pitch (fp32 elems)
#define BPh 40    // B pitch (half elems) -> 80B rows
#define HPh 136   // H pitch (half elems) -> 272B rows
#define YP 132    // Y pitch (fp32 elems)

#define ASZ 10240            // 64*40*4 per A stage
#define BSZ 10240            // 128*40*2 per B stage
#define OFF_AS 0             // 3 A stages: 0..30720
#define OFF_BS 30720         // 3 B stages: 30720..61440
#define OFF_HS 0             // H fp16: 64*136*2 = 17408 (overlaps dead A)
#define OFF_Y  0             // Y fp32: 64*132*4 = 33792 (overlaps A + dead B head)
#define OFF_IS 61440
#define OFF_ID 61696
#define SMEM_BYTES 61952

__device__ float g_agg[(size_t)NM * DD];
// fp16 transposed weights: eW0t(128x384), eW1t, sW0t, sW1t, dW0t(128x256), dW1t
__device__ __half g_wh[147456];
// precomputed node projections: U = grid @ W0b (fp16), V = mesh @ W0c (fp16)
__device__ __half g_u[(size_t)NG * DD];
__device__ __half g_v[(size_t)NM * DD];

__global__ void zero_agg_kernel() {
    size_t n = (size_t)NM * DD / 4;
    float4 z = make_float4(0.f, 0.f, 0.f, 0.f);
    float4* p = (float4*)g_agg;
    for (size_t i = blockIdx.x * (size_t)blockDim.x + threadIdx.x; i < n;
         i += (size_t)gridDim.x * blockDim.x) p[i] = z;
}

__global__ void prep_weights(const float* __restrict__ eW0, const float* __restrict__ eW1,
                             const float* __restrict__ sW0, const float* __restrict__ sW1,
                             const float* __restrict__ dW0, const float* __restrict__ dW1) {
    int i = blockIdx.x * blockDim.x + threadIdx.x;
    if (i >= 147456) return;
    float v;
    if (i < 49152)       { int j = i;          v = eW0[(j % 384) * 128 + (j / 384)]; }
    else if (i < 65536)  { int j = i - 49152;  v = eW1[(j % 128) * 128 + (j / 128)]; }
    else if (i < 81920)  { int j = i - 65536;  v = sW0[(j % 128) * 128 + (j / 128)]; }
    else if (i < 98304)  { int j = i - 81920;  v = sW1[(j % 128) * 128 + (j / 128)]; }
    else if (i < 131072) { int j = i - 98304;  v = dW0[(j % 256) * 128 + (j / 256)]; }
    else                 { int j = i - 131072; v = dW1[(j % 128) * 128 + (j / 128)]; }
    g_wh[i] = __float2half_rn(v);
}

__device__ __forceinline__ void cp16(unsigned saddr, const void* g, bool pred) {
    int sz = pred ? 16 : 0;
    asm volatile("cp.async.cg.shared.global [%0], [%1], 16, %2;\n"
                 :: "r"(saddr), "l"(g), "r"(sz));
}
#define CP_COMMIT asm volatile("cp.async.commit_group;\n")
template <int N>
__device__ __forceinline__ void cp_wait() {
    asm volatile("cp.async.wait_group %0;\n" :: "n"(N));
}

__device__ __forceinline__ unsigned packh2(float lo, float hi) {
    unsigned r;
    asm("cvt.rn.f16x2.f32 %0, %1, %2;" : "=r"(r) : "f"(hi), "f"(lo));
    return r;
}

__device__ __forceinline__ void ldsm4(unsigned& r0, unsigned& r1, unsigned& r2, unsigned& r3,
                                      unsigned addr) {
    asm volatile("ldmatrix.sync.aligned.m8n8.x4.shared.b16 {%0,%1,%2,%3}, [%4];"
                 : "=r"(r0), "=r"(r1), "=r"(r2), "=r"(r3) : "r"(addr));
}

__device__ __forceinline__ void mma16(float* d, const unsigned* a, unsigned b0, unsigned b1) {
    asm volatile(
        "mma.sync.aligned.m16n8k16.row.col.f32.f16.f16.f32 "
        "{%0,%1,%2,%3}, {%4,%5,%6,%7}, {%8,%9}, {%0,%1,%2,%3};\n"
        : "+f"(d[0]), "+f"(d[1]), "+f"(d[2]), "+f"(d[3])
        : "r"(a[0]), "r"(a[1]), "r"(a[2]), "r"(a[3]), "r"(b0), "r"(b1));
}

// MODE 0: edge MLP  (efeat@W0a + U[src] + V[dst] -> SiLU -> GEMM2 -> LN -> red scatter)
// MODE 1: plain MLP (Xa -> resid + out)
// MODE 2: dst MLP   (concat(agg, mesh) -> resid + out)
// MODE 3: projection (Xa @ W0t-slice -> fp16 outh, no bias/act)
// KW: row stride (in halves) of the W0t matrix the B-loader reads
template <int K1, int MODE, int KW>
__global__ __launch_bounds__(NTH, 3)
void mlp_tc(const float* __restrict__ Xa,
            const float* __restrict__ Xb,
            const int* __restrict__ src_idx,
            const int* __restrict__ dst_idx,
            const __half* __restrict__ Uh,   // MODE 0: precomputed grid proj
            const __half* __restrict__ Vh,   // MODE 0: precomputed mesh proj
            const __half* __restrict__ W0t, const float* __restrict__ b0v,
            const __half* __restrict__ W1t, const float* __restrict__ b1v,
            const float* __restrict__ gamma, const float* __restrict__ beta,
            const float* __restrict__ resid,
            float* __restrict__ out,
            __half* __restrict__ outh,
            float* __restrict__ agg,
            int R)
{
    extern __shared__ unsigned char smem[];
    unsigned* Hu = (unsigned*)(smem + OFF_HS);
    float*    Ys = (float*)(smem + OFF_Y);
    int*      Is = (int*)(smem + OFF_IS);
    int*      Id = (int*)(smem + OFF_ID);
    const unsigned sbase = (unsigned)__cvta_generic_to_shared(smem);

    const int t   = threadIdx.x;
    const int wid = t >> 5;
    const int l   = t & 31;
    const int lr  = l >> 2;
    const int lc  = l & 3;
    const int warpM = wid >> 1;          // 0..3 -> 16 rows each
    const int warpN = wid & 1;           // 0..1 -> 64 cols each
    const int wr0 = warpM * 16;
    const int wc0 = warpN * 64;
    const int rowBase = blockIdx.x * BLK_R;

    // ldmatrix lane-address bases
    const int mi = l >> 3;
    const int rr = l & 7;
    const unsigned baseB = sbase + OFF_BS
        + 80u * (unsigned)(wc0 + 8 * (mi >> 1) + rr) + 16u * (unsigned)(mi & 1);
    const unsigned baseH = sbase + OFF_HS
        + 272u * (unsigned)(wr0 + 8 * (mi & 1) + rr) + 16u * (unsigned)(mi >> 1);

    if (MODE == 0) {
        if (t < 64) {
            Is[t] = src_idx[rowBase + t];
            Id[t] = dst_idx[rowBase + t];
        }
        __syncthreads();
    }

    // ---- async tile loaders ----
    auto load_a = [&](int k0, int buf) {
#pragma unroll
        for (int j = 0; j < 2; ++j) {
            int idx = t + j * 256;
            int r   = idx >> 3;          // 0..63
            int c4  = (idx & 7) * 4;     // 0..28
            int rg  = rowBase + r;
            bool pred = (MODE == 0) ? true : (rg < R);
            int rgc = pred ? rg : (R - 1);
            const float* src;
            if (MODE == 0) {
                src = Xa + (size_t)rg * 128 + k0 + c4;       // efeat only, contiguous
            } else if (MODE == 1 || MODE == 3) {
                src = Xa + (size_t)rgc * 128 + k0 + c4;
            } else { // MODE 2
                int seg = k0 >> 7;
                int cc  = (k0 & 127) + c4;
                src = (seg == 0) ? Xa + (size_t)rgc * 128 + cc
                                 : Xb + (size_t)rgc * 128 + cc;
            }
            cp16(sbase + OFF_AS + (unsigned)buf * ASZ + (unsigned)(r * AP + c4) * 4u, src, pred);
        }
    };
    auto load_b = [&](const __half* Wt, int KS, int k0, int buf) {
#pragma unroll
        for (int j = 0; j < 2; ++j) {
            int idx = t + j * 256;
            int n = idx >> 2;
            int ch = idx & 3;
            cp16(sbase + OFF_BS + (unsigned)buf * BSZ + (unsigned)(n * BPh * 2 + ch * 16),
                 Wt + (size_t)n * KS + k0 + ch * 8, true);
        }
    };

    constexpr int NCH1 = K1 / KC;
    constexpr int NCH2 = 4;

    // ---------------- GEMM1: acc = f16(X) @ W0t ----------------
    float acc[8][4];
#pragma unroll
    for (int n = 0; n < 8; ++n)
#pragma unroll
        for (int j = 0; j < 4; ++j) acc[n][j] = 0.0f;

    load_a(0, 0); load_b(W0t, KW, 0, 0); CP_COMMIT;
    load_a(KC, 1); load_b(W0t, KW, KC, 1); CP_COMMIT;

#pragma unroll 1
    for (int kb = 0; kb < NCH1; ++kb) {
        // Tail-safety: when nothing is committed behind the chunk we're about
        // to consume (MODE 3 tail), drain ALL groups; wait_group<1> with a
        // single pending group is a no-op and races the last chunk.
        if (MODE == 3 && kb == NCH1 - 1) cp_wait<0>(); else cp_wait<1>();
        __syncthreads();
        int p = kb + 2;
        if (p < NCH1) {
            load_a(p * KC, p % 3); load_b(W0t, KW, p * KC, p % 3); CP_COMMIT;
        } else if (MODE != 3 && p - NCH1 < NCH2) {
            load_b(W1t, 128, (p - NCH1) * KC, p % 3); CP_COMMIT;
        }
        const int bufc = kb % 3;
        const float* Af = (const float*)(smem + OFF_AS + bufc * ASZ);
        const unsigned bB = baseB + (unsigned)bufc * BSZ;
#pragma unroll
        for (int ks = 0; ks < 2; ++ks) {
            unsigned bfr[8][2];
#pragma unroll
            for (int g = 0; g < 4; ++g)
                ldsm4(bfr[2 * g][0], bfr[2 * g][1], bfr[2 * g + 1][0], bfr[2 * g + 1][1],
                      bB + 1280u * g + 32u * ks);
            unsigned a[4];
            int c0 = ks * 16 + 2 * lc;
            {
                int r = wr0 + lr;
                float2 f0 = *(const float2*)&Af[r * AP + c0];
                float2 f1 = *(const float2*)&Af[(r + 8) * AP + c0];
                float2 f2 = *(const float2*)&Af[r * AP + c0 + 8];
                float2 f3 = *(const float2*)&Af[(r + 8) * AP + c0 + 8];
                a[0] = packh2(f0.x, f0.y);
                a[1] = packh2(f1.x, f1.y);
                a[2] = packh2(f2.x, f2.y);
                a[3] = packh2(f3.x, f3.y);
            }
#pragma unroll
            for (int nt = 0; nt < 8; ++nt)
                mma16(acc[nt], a, bfr[nt][0], bfr[nt][1]);
        }
    }

    if (MODE == 3) {
        // write raw projection as fp16
#pragma unroll
        for (int nt = 0; nt < 8; ++nt) {
            int c  = wc0 + nt * 8 + 2 * lc;
            int r1 = rowBase + wr0 + lr;
            int r2 = r1 + 8;
            if (r1 < R)
                *(__half2*)&outh[(size_t)r1 * 128 + c] = __floats2half2_rn(acc[nt][0], acc[nt][1]);
            if (r2 < R)
                *(__half2*)&outh[(size_t)r2 * 128 + c] = __floats2half2_rn(acc[nt][2], acc[nt][3]);
        }
        return;
    }

    if (MODE == 0) {
        // add gathered node projections U[src] + V[dst] (fp16 -> fp32)
        int i1 = Is[wr0 + lr], i2 = Is[wr0 + 8 + lr];
        int d1 = Id[wr0 + lr], d2 = Id[wr0 + 8 + lr];
#pragma unroll
        for (int nt = 0; nt < 8; ++nt) {
            int c = wc0 + nt * 8 + 2 * lc;
            float2 u1 = __half22float2(*(const __half2*)&Uh[(size_t)i1 * 128 + c]);
            float2 u2 = __half22float2(*(const __half2*)&Uh[(size_t)i2 * 128 + c]);
            float2 v1 = __half22float2(*(const __half2*)&Vh[(size_t)d1 * 128 + c]);
            float2 v2 = __half22float2(*(const __half2*)&Vh[(size_t)d2 * 128 + c]);
            acc[nt][0] += u1.x + v1.x;
            acc[nt][1] += u1.y + v1.y;
            acc[nt][2] += u2.x + v2.x;
            acc[nt][3] += u2.y + v2.y;
        }
    }
    __syncthreads();   // all warps done with A stages before H overwrites them

    // bias + SiLU -> H (fp16, overlaps dead A region)
#pragma unroll
    for (int nt = 0; nt < 8; ++nt) {
        int c  = wc0 + nt * 8 + 2 * lc;
        float2 bb = *(const float2*)&b0v[c];
        int r1 = wr0 + lr;
        int r2 = r1 + 8;
        float x0 = acc[nt][0] + bb.x;
        float x1 = acc[nt][1] + bb.y;
        float x2 = acc[nt][2] + bb.x;
        float x3 = acc[nt][3] + bb.y;
        float s0 = x0 / (1.0f + __expf(-x0));
        float s1 = x1 / (1.0f + __expf(-x1));
        float s2 = x2 / (1.0f + __expf(-x2));
        float s3 = x3 / (1.0f + __expf(-x3));
        Hu[(r1 * HPh + c) >> 1] = packh2(s0, s1);
        Hu[(r2 * HPh + c) >> 1] = packh2(s2, s3);
    }
    __syncthreads();

    // ---------------- GEMM2: y = H @ W1t ----------------
    float acc2[8][4];
#pragma unroll
    for (int n = 0; n < 8; ++n)
#pragma unroll
        for (int j = 0; j < 4; ++j) acc2[n][j] = 0.0f;

#pragma unroll 1
    for (int j = 0; j < NCH2; ++j) {
        // Tail-safety: last chunk has nothing committed behind it -> full drain.
        if (j == NCH2 - 1) cp_wait<0>(); else cp_wait<1>();
        __syncthreads();
        if (j + 2 < NCH2) { load_b(W1t, 128, (j + 2) * KC, (NCH1 + j + 2) % 3); CP_COMMIT; }
        const int bufc = (NCH1 + j) % 3;
        const unsigned bB = baseB + (unsigned)bufc * BSZ;
#pragma unroll
        for (int ks = 0; ks < 2; ++ks) {
            unsigned bfr[8][2];
#pragma unroll
            for (int g = 0; g < 4; ++g)
                ldsm4(bfr[2 * g][0], bfr[2 * g][1], bfr[2 * g + 1][0], bfr[2 * g + 1][1],
                      bB + 1280u * g + 32u * ks);
            unsigned a[4];
            ldsm4(a[0], a[1], a[2], a[3], baseH + 64u * j + 32u * ks);
#pragma unroll
            for (int nt = 0; nt < 8; ++nt)
                mma16(acc2[nt], a, bfr[nt][0], bfr[nt][1]);
        }
    }
    __syncthreads();   // all compute done before Y overwrites A/B regions

    // y = acc2 + b1 -> Y (fp32)
#pragma unroll
    for (int nt = 0; nt < 8; ++nt) {
        int c  = wc0 + nt * 8 + 2 * lc;
        float2 bb = *(const float2*)&b1v[c];
        int r1 = wr0 + lr;
        int r2 = r1 + 8;
        float2 y1; y1.x = acc2[nt][0] + bb.x; y1.y = acc2[nt][1] + bb.y;
        float2 y2; y2.x = acc2[nt][2] + bb.x; y2.y = acc2[nt][3] + bb.y;
        *(float2*)&Ys[r1 * YP + c] = y1;
        *(float2*)&Ys[r2 * YP + c] = y2;
    }
    __syncthreads();

    // ---------------- LayerNorm + epilogue (warp w owns rows w*8..w*8+7) ----------------
    float4 gg = *(const float4*)&gamma[l * 4];
    float4 bt = *(const float4*)&beta[l * 4];

#pragma unroll 4
    for (int i = 0; i < 8; ++i) {
        int r  = wid * 8 + i;
        int rg = rowBase + r;
        float4 v = *(const float4*)&Ys[r * YP + l * 4];
        float s  = v.x + v.y + v.z + v.w;
        float ss = v.x * v.x + v.y * v.y + v.z * v.z + v.w * v.w;
#pragma unroll
        for (int off = 16; off > 0; off >>= 1) {
            s  += __shfl_xor_sync(0xFFFFFFFFu, s,  off);
            ss += __shfl_xor_sync(0xFFFFFFFFu, ss, off);
        }
        float mean = s * (1.0f / DD);
        float var  = ss * (1.0f / DD) - mean * mean;
        float rstd = rsqrtf(var + 1e-5f);

        float4 o;
        o.x = (v.x - mean) * rstd * gg.x + bt.x;
        o.y = (v.y - mean) * rstd * gg.y + bt.y;
        o.z = (v.z - mean) * rstd * gg.z + bt.z;
        o.w = (v.w - mean) * rstd * gg.w + bt.w;

        if (MODE == 0) {
            float* p = &agg[(size_t)Id[r] * DD + l * 4];
            asm volatile("red.global.add.v4.f32 [%0], {%1,%2,%3,%4};"
                         :: "l"(p), "f"(o.x), "f"(o.y), "f"(o.z), "f"(o.w)
                         : "memory");
        } else {
            if (rg < R) {
                float4 rv = *(const float4*)&resid[(size_t)rg * DD + l * 4];
                o.x += rv.x; o.y += rv.y; o.z += rv.z; o.w += rv.w;
                *(float4*)&out[(size_t)rg * DD + l * 4] = o;
            }
        }
    }
}

extern "C" void kernel_launch(void* const* d_in, const int* in_sizes, int n_in,
                              void* d_out, int out_size)
{
    const float* efeat   = (const float*)d_in[0];
    const float* grid    = (const float*)d_in[1];
    const float* mesh    = (const float*)d_in[2];
    const int*   src_idx = (const int*)d_in[3];
    const int*   dst_idx = (const int*)d_in[4];
    const float* eW0 = (const float*)d_in[5];
    const float* eb0 = (const float*)d_in[6];
    const float* eW1 = (const float*)d_in[7];
    const float* eb1 = (const float*)d_in[8];
    const float* eg  = (const float*)d_in[9];
    const float* ebt = (const float*)d_in[10];
    const float* sW0 = (const float*)d_in[11];
    const float* sb0 = (const float*)d_in[12];
    const float* sW1 = (const float*)d_in[13];
    const float* sb1 = (const float*)d_in[14];
    const float* sg  = (const float*)d_in[15];
    const float* sbt = (const float*)d_in[16];
    const float* dW0 = (const float*)d_in[17];
    const float* db0 = (const float*)d_in[18];
    const float* dW1 = (const float*)d_in[19];
    const float* db1 = (const float*)d_in[20];
    const float* dg  = (const float*)d_in[21];
    const float* dbt = (const float*)d_in[22];

    float* out_grid = (float*)d_out;
    float* out_mesh = (float*)d_out + (size_t)NG * DD;

    float* agg_ptr = nullptr;
    cudaGetSymbolAddress((void**)&agg_ptr, g_agg);
    __half* wh_ptr = nullptr;
    cudaGetSymbolAddress((void**)&wh_ptr, g_wh);
    __half* u_ptr = nullptr;
    cudaGetSymbolAddress((void**)&u_ptr, g_u);
    __half* v_ptr = nullptr;
    cudaGetSymbolAddress((void**)&v_ptr, g_v);

    static bool attr_done = false;
    if (!attr_done) {
        cudaFuncSetAttribute(mlp_tc<128, 0, 384>, cudaFuncAttributeMaxDynamicSharedMemorySize, SMEM_BYTES);
        cudaFuncSetAttribute(mlp_tc<128, 1, 128>, cudaFuncAttributeMaxDynamicSharedMemorySize, SMEM_BYTES);
        cudaFuncSetAttribute(mlp_tc<256, 2, 256>, cudaFuncAttributeMaxDynamicSharedMemorySize, SMEM_BYTES);
        cudaFuncSetAttribute(mlp_tc<128, 3, 384>, cudaFuncAttributeMaxDynamicSharedMemorySize, SMEM_BYTES);
        attr_done = true;
    }

    prep_weights<<<576, 256>>>(eW0, eW1, sW0, sW1, dW0, dW1);
    zero_agg_kernel<<<512, 256>>>();

    const __half* weW0t = wh_ptr;            // [128n][384k], k 0..127 = efeat part
    const __half* weW1t = wh_ptr + 49152;
    const __half* wsW0t = wh_ptr + 65536;
    const __half* wsW1t = wh_ptr + 81920;
    const __half* wdW0t = wh_ptr + 98304;
    const __half* wdW1t = wh_ptr + 131072;

    // P1: U = grid @ W0b  (k slice 128..255 of eW0t, row stride 384)
    mlp_tc<128, 3, 384><<<NG / BLK_R, NTH, SMEM_BYTES>>>(
        grid, nullptr, nullptr, nullptr, nullptr, nullptr,
        weW0t + 128, nullptr, nullptr, nullptr, nullptr, nullptr,
        nullptr, nullptr, u_ptr, nullptr, NG);

    // P2: V = mesh @ W0c  (k slice 256..383 of eW0t, row stride 384)
    mlp_tc<128, 3, 384><<<(NM + BLK_R - 1) / BLK_R, NTH, SMEM_BYTES>>>(
        mesh, nullptr, nullptr, nullptr, nullptr, nullptr,
        weW0t + 256, nullptr, nullptr, nullptr, nullptr, nullptr,
        nullptr, nullptr, v_ptr, nullptr, NM);

    // edge MLP + scatter-sum (efeat slice: k 0..127 of eW0t, row stride 384)
    mlp_tc<128, 0, 384><<<NE / BLK_R, NTH, SMEM_BYTES>>>(
        efeat, nullptr, src_idx, dst_idx, u_ptr, v_ptr,
        weW0t, eb0, weW1t, eb1, eg, ebt,
        nullptr, nullptr, nullptr, agg_ptr, NE);

    // src (grid) node MLP with residual
    mlp_tc<128, 1, 128><<<NG / BLK_R, NTH, SMEM_BYTES>>>(
        grid, nullptr, nullptr, nullptr, nullptr, nullptr,
        wsW0t, sb0, wsW1t, sb1, sg, sbt,
        grid, out_grid, nullptr, nullptr, NG);

    // dst (mesh) node MLP with residual
    mlp_tc<256, 2, 256><<<(NM + BLK_R - 1) / BLK_R, NTH, SMEM_BYTES>>>(
        agg_ptr, mesh, nullptr, nullptr, nullptr, nullptr,
        wdW0t, db0, wdW1t, db1, dg, dbt,
        mesh, out_mesh, nullptr, nullptr, NM);
}

// round 13
// speedup vs baseline: 1.1142x; 1.0261x over previous
#include <cuda_runtime.h>
#include <cuda_fp16.h>
#include <math.h>

#define NG 131072
#define NM 40962
#define NE 524288
#define DD 128

#define BLK_R 64
#define KC 32
#define NTH 256

#define NGB (NG / BLK_R)      // 2048
#define NMB ((NM + BLK_R - 1) / BLK_R)  // 641
#define NEB (NE / BLK_R)      // 8192
#define ZB  128               // zero-agg blocks in kernel A

#define AP 40     // A pitch (fp32 elems)
#define BPh 40    // B pitch (half elems) -> 80B rows
#define HPh 136   // H pitch (half elems) -> 272B rows
#define YP 132    // Y pitch (fp32 elems)

#define ASZ 10240            // 64*40*4 per A stage
#define BSZ 10240            // 128*40*2 per B stage
#define OFF_AS 0             // 3 A stages: 0..30720
#define OFF_BS 30720         // 3 B stages: 30720..61440
#define OFF_HS 0             // H fp16: 64*136*2 = 17408 (overlaps dead A)
#define OFF_Y  0             // Y fp32: 64*132*4 = 33792 (overlaps A + dead B head)
#define OFF_IS 61440
#define OFF_ID 61696
#define SMEM_BYTES 61952

__device__ float g_agg[(size_t)NM * DD];
// fp16 transposed weights: eW0t(128x384), eW1t, sW0t, sW1t, dW0t(128x256), dW1t
__device__ __half g_wh[147456];
// precomputed node projections: U = grid @ W0b (fp16), V = mesh @ W0c (fp16)
__device__ __half g_u[(size_t)NG * DD];
__device__ __half g_v[(size_t)NM * DD];

__global__ void prep_weights(const float* __restrict__ eW0, const float* __restrict__ eW1,
                             const float* __restrict__ sW0, const float* __restrict__ sW1,
                             const float* __restrict__ dW0, const float* __restrict__ dW1) {
    int i = blockIdx.x * blockDim.x + threadIdx.x;
    if (i >= 147456) return;
    float v;
    if (i < 49152)       { int j = i;          v = eW0[(j % 384) * 128 + (j / 384)]; }
    else if (i < 65536)  { int j = i - 49152;  v = eW1[(j % 128) * 128 + (j / 128)]; }
    else if (i < 81920)  { int j = i - 65536;  v = sW0[(j % 128) * 128 + (j / 128)]; }
    else if (i < 98304)  { int j = i - 81920;  v = sW1[(j % 128) * 128 + (j / 128)]; }
    else if (i < 131072) { int j = i - 98304;  v = dW0[(j % 256) * 128 + (j / 256)]; }
    else                 { int j = i - 131072; v = dW1[(j % 128) * 128 + (j / 128)]; }
    g_wh[i] = __float2half_rn(v);
}

__device__ __forceinline__ void cp16(unsigned saddr, const void* g, bool pred) {
    int sz = pred ? 16 : 0;
    asm volatile("cp.async.cg.shared.global [%0], [%1], 16, %2;\n"
                 :: "r"(saddr), "l"(g), "r"(sz));
}
#define CP_COMMIT asm volatile("cp.async.commit_group;\n")
template <int N>
__device__ __forceinline__ void cp_wait() {
    asm volatile("cp.async.wait_group %0;\n" :: "n"(N));
}

__device__ __forceinline__ unsigned packh2(float lo, float hi) {
    unsigned r;
    asm("cvt.rn.f16x2.f32 %0, %1, %2;" : "=r"(r) : "f"(hi), "f"(lo));
    return r;
}

__device__ __forceinline__ void ldsm4(unsigned& r0, unsigned& r1, unsigned& r2, unsigned& r3,
                                      unsigned addr) {
    asm volatile("ldmatrix.sync.aligned.m8n8.x4.shared.b16 {%0,%1,%2,%3}, [%4];"
                 : "=r"(r0), "=r"(r1), "=r"(r2), "=r"(r3) : "r"(addr));
}

__device__ __forceinline__ void mma16(float* d, const unsigned* a, unsigned b0, unsigned b1) {
    asm volatile(
        "mma.sync.aligned.m16n8k16.row.col.f32.f16.f16.f32 "
        "{%0,%1,%2,%3}, {%4,%5,%6,%7}, {%8,%9}, {%0,%1,%2,%3};\n"
        : "+f"(d[0]), "+f"(d[1]), "+f"(d[2]), "+f"(d[3])
        : "r"(a[0]), "r"(a[1]), "r"(a[2]), "r"(a[3]), "r"(b0), "r"(b1));
}

// MODE 0: edge MLP  (efeat@W0a + U[src] + V[dst] -> SiLU -> GEMM2 -> LN -> red scatter)
// MODE 1: plain MLP (Xa -> resid + out)
// MODE 2: dst MLP   (concat(agg, mesh) -> resid + out)
// MODE 3: projection (Xa @ W0t-slice -> fp16 outh, no bias/act)
// KW: row stride (in halves) of the W0t matrix the B-loader reads
template <int K1, int MODE, int KW>
__device__ __forceinline__
void mlp_body(const float* __restrict__ Xa,
              const float* __restrict__ Xb,
              const int* __restrict__ src_idx,
              const int* __restrict__ dst_idx,
              const __half* __restrict__ Uh,
              const __half* __restrict__ Vh,
              const __half* __restrict__ W0t, const float* __restrict__ b0v,
              const __half* __restrict__ W1t, const float* __restrict__ b1v,
              const float* __restrict__ gamma, const float* __restrict__ beta,
              const float* __restrict__ resid,
              float* __restrict__ out,
              __half* __restrict__ outh,
              float* __restrict__ agg,
              int rowBase, int R)
{
    extern __shared__ unsigned char smem[];
    unsigned* Hu = (unsigned*)(smem + OFF_HS);
    float*    Ys = (float*)(smem + OFF_Y);
    int*      Is = (int*)(smem + OFF_IS);
    int*      Id = (int*)(smem + OFF_ID);
    const unsigned sbase = (unsigned)__cvta_generic_to_shared(smem);

    const int t   = threadIdx.x;
    const int wid = t >> 5;
    const int l   = t & 31;
    const int lr  = l >> 2;
    const int lc  = l & 3;
    const int warpM = wid >> 1;          // 0..3 -> 16 rows each
    const int warpN = wid & 1;           // 0..1 -> 64 cols each
    const int wr0 = warpM * 16;
    const int wc0 = warpN * 64;

    // ldmatrix lane-address bases
    const int mi = l >> 3;
    const int rr = l & 7;
    const unsigned baseB = sbase + OFF_BS
        + 80u * (unsigned)(wc0 + 8 * (mi >> 1) + rr) + 16u * (unsigned)(mi & 1);
    const unsigned baseH = sbase + OFF_HS
        + 272u * (unsigned)(wr0 + 8 * (mi & 1) + rr) + 16u * (unsigned)(mi >> 1);

    if (MODE == 0) {
        if (t < 64) {
            Is[t] = src_idx[rowBase + t];
            Id[t] = dst_idx[rowBase + t];
        }
        __syncthreads();
        // L2-prefetch the gathered U/V rows; consumed right after GEMM1.
        if (t < 64) {
            const char* pu = (const char*)(Uh + (size_t)Is[t] * 128);
            asm volatile("prefetch.global.L2 [%0];" :: "l"(pu));
            asm volatile("prefetch.global.L2 [%0+128];" :: "l"(pu));
        } else if (t < 128) {
            const char* pv = (const char*)(Vh + (size_t)Id[t - 64] * 128);
            asm volatile("prefetch.global.L2 [%0];" :: "l"(pv));
            asm volatile("prefetch.global.L2 [%0+128];" :: "l"(pv));
        }
    }

    // ---- async tile loaders ----
    auto load_a = [&](int k0, int buf) {
#pragma unroll
        for (int j = 0; j < 2; ++j) {
            int idx = t + j * 256;
            int r   = idx >> 3;          // 0..63
            int c4  = (idx & 7) * 4;     // 0..28
            int rg  = rowBase + r;
            bool pred = (MODE == 0) ? true : (rg < R);
            int rgc = pred ? rg : (R - 1);
            const float* src;
            if (MODE == 0) {
                src = Xa + (size_t)rg * 128 + k0 + c4;       // efeat only, contiguous
            } else if (MODE == 1 || MODE == 3) {
                src = Xa + (size_t)rgc * 128 + k0 + c4;
            } else { // MODE 2
                int seg = k0 >> 7;
                int cc  = (k0 & 127) + c4;
                src = (seg == 0) ? Xa + (size_t)rgc * 128 + cc
                                 : Xb + (size_t)rgc * 128 + cc;
            }
            cp16(sbase + OFF_AS + (unsigned)buf * ASZ + (unsigned)(r * AP + c4) * 4u, src, pred);
        }
    };
    auto load_b = [&](const __half* Wt, int KS, int k0, int buf) {
#pragma unroll
        for (int j = 0; j < 2; ++j) {
            int idx = t + j * 256;
            int n = idx >> 2;
            int ch = idx & 3;
            cp16(sbase + OFF_BS + (unsigned)buf * BSZ + (unsigned)(n * BPh * 2 + ch * 16),
                 Wt + (size_t)n * KS + k0 + ch * 8, true);
        }
    };

    constexpr int NCH1 = K1 / KC;
    constexpr int NCH2 = 4;

    // ---------------- GEMM1: acc = f16(X) @ W0t ----------------
    float acc[8][4];
#pragma unroll
    for (int n = 0; n < 8; ++n)
#pragma unroll
        for (int j = 0; j < 4; ++j) acc[n][j] = 0.0f;

    load_a(0, 0); load_b(W0t, KW, 0, 0); CP_COMMIT;
    load_a(KC, 1); load_b(W0t, KW, KC, 1); CP_COMMIT;

#pragma unroll 1
    for (int kb = 0; kb < NCH1; ++kb) {
        // Tail-safety: when nothing is committed behind the chunk being
        // consumed (MODE 3 tail), drain ALL groups.
        if (MODE == 3 && kb == NCH1 - 1) cp_wait<0>(); else cp_wait<1>();
        __syncthreads();
        int p = kb + 2;
        if (p < NCH1) {
            load_a(p * KC, p % 3); load_b(W0t, KW, p * KC, p % 3); CP_COMMIT;
        } else if (MODE != 3 && p - NCH1 < NCH2) {
            load_b(W1t, 128, (p - NCH1) * KC, p % 3); CP_COMMIT;
        }
        const int bufc = kb % 3;
        const float* Af = (const float*)(smem + OFF_AS + bufc * ASZ);
        const unsigned bB = baseB + (unsigned)bufc * BSZ;
#pragma unroll
        for (int ks = 0; ks < 2; ++ks) {
            unsigned bfr[8][2];
#pragma unroll
            for (int g = 0; g < 4; ++g)
                ldsm4(bfr[2 * g][0], bfr[2 * g][1], bfr[2 * g + 1][0], bfr[2 * g + 1][1],
                      bB + 1280u * g + 32u * ks);
            unsigned a[4];
            int c0 = ks * 16 + 2 * lc;
            {
                int r = wr0 + lr;
                float2 f0 = *(const float2*)&Af[r * AP + c0];
                float2 f1 = *(const float2*)&Af[(r + 8) * AP + c0];
                float2 f2 = *(const float2*)&Af[r * AP + c0 + 8];
                float2 f3 = *(const float2*)&Af[(r + 8) * AP + c0 + 8];
                a[0] = packh2(f0.x, f0.y);
                a[1] = packh2(f1.x, f1.y);
                a[2] = packh2(f2.x, f2.y);
                a[3] = packh2(f3.x, f3.y);
            }
#pragma unroll
            for (int nt = 0; nt < 8; ++nt)
                mma16(acc[nt], a, bfr[nt][0], bfr[nt][1]);
        }
    }

    if (MODE == 3) {
        // write raw projection as fp16
#pragma unroll
        for (int nt = 0; nt < 8; ++nt) {
            int c  = wc0 + nt * 8 + 2 * lc;
            int r1 = rowBase + wr0 + lr;
            int r2 = r1 + 8;
            if (r1 < R)
                *(__half2*)&outh[(size_t)r1 * 128 + c] = __floats2half2_rn(acc[nt][0], acc[nt][1]);
            if (r2 < R)
                *(__half2*)&outh[(size_t)r2 * 128 + c] = __floats2half2_rn(acc[nt][2], acc[nt][3]);
        }
        return;
    }

    if (MODE == 0) {
        // add gathered node projections U[src] + V[dst] (fp16 -> fp32)
        int i1 = Is[wr0 + lr], i2 = Is[wr0 + 8 + lr];
        int d1 = Id[wr0 + lr], d2 = Id[wr0 + 8 + lr];
#pragma unroll
        for (int nt = 0; nt < 8; ++nt) {
            int c = wc0 + nt * 8 + 2 * lc;
            float2 u1 = __half22float2(*(const __half2*)&Uh[(size_t)i1 * 128 + c]);
            float2 u2 = __half22float2(*(const __half2*)&Uh[(size_t)i2 * 128 + c]);
            float2 v1 = __half22float2(*(const __half2*)&Vh[(size_t)d1 * 128 + c]);
            float2 v2 = __half22float2(*(const __half2*)&Vh[(size_t)d2 * 128 + c]);
            acc[nt][0] += u1.x + v1.x;
            acc[nt][1] += u1.y + v1.y;
            acc[nt][2] += u2.x + v2.x;
            acc[nt][3] += u2.y + v2.y;
        }
    }
    __syncthreads();   // all warps done with A stages before H overwrites them

    // bias + SiLU -> H (fp16, overlaps dead A region)
#pragma unroll
    for (int nt = 0; nt < 8; ++nt) {
        int c  = wc0 + nt * 8 + 2 * lc;
        float2 bb = *(const float2*)&b0v[c];
        int r1 = wr0 + lr;
        int r2 = r1 + 8;
        float x0 = acc[nt][0] + bb.x;
        float x1 = acc[nt][1] + bb.y;
        float x2 = acc[nt][2] + bb.x;
        float x3 = acc[nt][3] + bb.y;
        float s0 = x0 / (1.0f + __expf(-x0));
        float s1 = x1 / (1.0f + __expf(-x1));
        float s2 = x2 / (1.0f + __expf(-x2));
        float s3 = x3 / (1.0f + __expf(-x3));
        Hu[(r1 * HPh + c) >> 1] = packh2(s0, s1);
        Hu[(r2 * HPh + c) >> 1] = packh2(s2, s3);
    }
    __syncthreads();

    // ---------------- GEMM2: y = H @ W1t ----------------
    float acc2[8][4];
#pragma unroll
    for (int n = 0; n < 8; ++n)
#pragma unroll
        for (int j = 0; j < 4; ++j) acc2[n][j] = 0.0f;

#pragma unroll 1
    for (int j = 0; j < NCH2; ++j) {
        // Tail-safety: last chunk has nothing committed behind it -> full drain.
        if (j == NCH2 - 1) cp_wait<0>(); else cp_wait<1>();
        __syncthreads();
        if (j + 2 < NCH2) { load_b(W1t, 128, (j + 2) * KC, (NCH1 + j + 2) % 3); CP_COMMIT; }
        const int bufc = (NCH1 + j) % 3;
        const unsigned bB = baseB + (unsigned)bufc * BSZ;
#pragma unroll
        for (int ks = 0; ks < 2; ++ks) {
            unsigned bfr[8][2];
#pragma unroll
            for (int g = 0; g < 4; ++g)
                ldsm4(bfr[2 * g][0], bfr[2 * g][1], bfr[2 * g + 1][0], bfr[2 * g + 1][1],
                      bB + 1280u * g + 32u * ks);
            unsigned a[4];
            ldsm4(a[0], a[1], a[2], a[3], baseH + 64u * j + 32u * ks);
#pragma unroll
            for (int nt = 0; nt < 8; ++nt)
                mma16(acc2[nt], a, bfr[nt][0], bfr[nt][1]);
        }
    }
    __syncthreads();   // all compute done before Y overwrites A/B regions

    // y = acc2 + b1 -> Y (fp32)
#pragma unroll
    for (int nt = 0; nt < 8; ++nt) {
        int c  = wc0 + nt * 8 + 2 * lc;
        float2 bb = *(const float2*)&b1v[c];
        int r1 = wr0 + lr;
        int r2 = r1 + 8;
        float2 y1; y1.x = acc2[nt][0] + bb.x; y1.y = acc2[nt][1] + bb.y;
        float2 y2; y2.x = acc2[nt][2] + bb.x; y2.y = acc2[nt][3] + bb.y;
        *(float2*)&Ys[r1 * YP + c] = y1;
        *(float2*)&Ys[r2 * YP + c] = y2;
    }
    __syncthreads();

    // ---------------- LayerNorm + epilogue (warp w owns rows w*8..w*8+7) ----------------
    float4 gg = *(const float4*)&gamma[l * 4];
    float4 bt = *(const float4*)&beta[l * 4];

#pragma unroll 4
    for (int i = 0; i < 8; ++i) {
        int r  = wid * 8 + i;
        int rg = rowBase + r;
        float4 v = *(const float4*)&Ys[r * YP + l * 4];
        float s  = v.x + v.y + v.z + v.w;
        float ss = v.x * v.x + v.y * v.y + v.z * v.z + v.w * v.w;
#pragma unroll
        for (int off = 16; off > 0; off >>= 1) {
            s  += __shfl_xor_sync(0xFFFFFFFFu, s,  off);
            ss += __shfl_xor_sync(0xFFFFFFFFu, ss, off);
        }
        float mean = s * (1.0f / DD);
        float var  = ss * (1.0f / DD) - mean * mean;
        float rstd = rsqrtf(var + 1e-5f);

        float4 o;
        o.x = (v.x - mean) * rstd * gg.x + bt.x;
        o.y = (v.y - mean) * rstd * gg.y + bt.y;
        o.z = (v.z - mean) * rstd * gg.z + bt.z;
        o.w = (v.w - mean) * rstd * gg.w + bt.w;

        if (MODE == 0) {
            float* p = &agg[(size_t)Id[r] * DD + l * 4];
            asm volatile("red.global.add.v4.f32 [%0], {%1,%2,%3,%4};"
                         :: "l"(p), "f"(o.x), "f"(o.y), "f"(o.z), "f"(o.w)
                         : "memory");
        } else {
            if (rg < R) {
                float4 rv = *(const float4*)&resid[(size_t)rg * DD + l * 4];
                o.x += rv.x; o.y += rv.y; o.z += rv.z; o.w += rv.w;
                *(float4*)&out[(size_t)rg * DD + l * 4] = o;
            }
        }
    }
}

// Kernel A: P1 (U=grid@W0b) blocks + P2 (V=mesh@W0c) blocks + agg-zero blocks
__global__ __launch_bounds__(NTH, 3)
void kernelA(const float* __restrict__ grid, const float* __restrict__ mesh,
             const __half* __restrict__ weW0t,
             __half* __restrict__ u_ptr, __half* __restrict__ v_ptr,
             float* __restrict__ agg)
{
    int b = blockIdx.x;
    if (b < NGB) {
        mlp_body<128, 3, 384>(grid, nullptr, nullptr, nullptr, nullptr, nullptr,
                              weW0t + 128, nullptr, nullptr, nullptr, nullptr, nullptr,
                              nullptr, nullptr, u_ptr, nullptr, b * BLK_R, NG);
    } else if (b < NGB + NMB) {
        mlp_body<128, 3, 384>(mesh, nullptr, nullptr, nullptr, nullptr, nullptr,
                              weW0t + 256, nullptr, nullptr, nullptr, nullptr, nullptr,
                              nullptr, nullptr, v_ptr, nullptr, (b - NGB) * BLK_R, NM);
    } else {
        int zb = b - NGB - NMB;
        size_t n = (size_t)NM * DD / 4;
        float4 z = make_float4(0.f, 0.f, 0.f, 0.f);
        float4* p = (float4*)agg;
        for (size_t i = (size_t)zb * NTH + threadIdx.x; i < n; i += (size_t)ZB * NTH)
            p[i] = z;
    }
}

// Kernel B: edge MLP blocks + src (grid) node MLP blocks
__global__ __launch_bounds__(NTH, 3)
void kernelB(const float* __restrict__ efeat, const float* __restrict__ grid,
             const int* __restrict__ src_idx, const int* __restrict__ dst_idx,
             const __half* __restrict__ u_ptr, const __half* __restrict__ v_ptr,
             const __half* __restrict__ weW0t, const float* __restrict__ eb0,
             const __half* __restrict__ weW1t, const float* __restrict__ eb1,
             const float* __restrict__ eg, const float* __restrict__ ebt,
             float* __restrict__ agg,
             const __half* __restrict__ wsW0t, const float* __restrict__ sb0,
             const __half* __restrict__ wsW1t, const float* __restrict__ sb1,
             const float* __restrict__ sg, const float* __restrict__ sbt,
             float* __restrict__ out_grid)
{
    int b = blockIdx.x;
    if (b < NEB) {
        mlp_body<128, 0, 384>(efeat, nullptr, src_idx, dst_idx, u_ptr, v_ptr,
                              weW0t, eb0, weW1t, eb1, eg, ebt,
                              nullptr, nullptr, nullptr, agg, b * BLK_R, NE);
    } else {
        mlp_body<128, 1, 128>(grid, nullptr, nullptr, nullptr, nullptr, nullptr,
                              wsW0t, sb0, wsW1t, sb1, sg, sbt,
                              grid, out_grid, nullptr, nullptr, (b - NEB) * BLK_R, NG);
    }
}

// Kernel C: dst (mesh) node MLP (depends on edge scatter)
__global__ __launch_bounds__(NTH, 3)
void kernelC(const float* __restrict__ agg, const float* __restrict__ mesh,
             const __half* __restrict__ wdW0t, const float* __restrict__ db0,
             const __half* __restrict__ wdW1t, const float* __restrict__ db1,
             const float* __restrict__ dg, const float* __restrict__ dbt,
             float* __restrict__ out_mesh)
{
    mlp_body<256, 2, 256>(agg, mesh, nullptr, nullptr, nullptr, nullptr,
                          wdW0t, db0, wdW1t, db1, dg, dbt,
                          mesh, out_mesh, nullptr, nullptr, blockIdx.x * BLK_R, NM);
}

extern "C" void kernel_launch(void* const* d_in, const int* in_sizes, int n_in,
                              void* d_out, int out_size)
{
    const float* efeat   = (const float*)d_in[0];
    const float* grid    = (const float*)d_in[1];
    const float* mesh    = (const float*)d_in[2];
    const int*   src_idx = (const int*)d_in[3];
    const int*   dst_idx = (const int*)d_in[4];
    const float* eW0 = (const float*)d_in[5];
    const float* eb0 = (const float*)d_in[6];
    const float* eW1 = (const float*)d_in[7];
    const float* eb1 = (const float*)d_in[8];
    const float* eg  = (const float*)d_in[9];
    const float* ebt = (const float*)d_in[10];
    const float* sW0 = (const float*)d_in[11];
    const float* sb0 = (const float*)d_in[12];
    const float* sW1 = (const float*)d_in[13];
    const float* sb1 = (const float*)d_in[14];
    const float* sg  = (const float*)d_in[15];
    const float* sbt = (const float*)d_in[16];
    const float* dW0 = (const float*)d_in[17];
    const float* db0 = (const float*)d_in[18];
    const float* dW1 = (const float*)d_in[19];
    const float* db1 = (const float*)d_in[20];
    const float* dg  = (const float*)d_in[21];
    const float* dbt = (const float*)d_in[22];

    float* out_grid = (float*)d_out;
    float* out_mesh = (float*)d_out + (size_t)NG * DD;

    float* agg_ptr = nullptr;
    cudaGetSymbolAddress((void**)&agg_ptr, g_agg);
    __half* wh_ptr = nullptr;
    cudaGetSymbolAddress((void**)&wh_ptr, g_wh);
    __half* u_ptr = nullptr;
    cudaGetSymbolAddress((void**)&u_ptr, g_u);
    __half* v_ptr = nullptr;
    cudaGetSymbolAddress((void**)&v_ptr, g_v);

    static bool attr_done = false;
    if (!attr_done) {
        cudaFuncSetAttribute(kernelA, cudaFuncAttributeMaxDynamicSharedMemorySize, SMEM_BYTES);
        cudaFuncSetAttribute(kernelB, cudaFuncAttributeMaxDynamicSharedMemorySize, SMEM_BYTES);
        cudaFuncSetAttribute(kernelC, cudaFuncAttributeMaxDynamicSharedMemorySize, SMEM_BYTES);
        attr_done = true;
    }

    const __half* weW0t = wh_ptr;            // [128n][384k], k 0..127 = efeat part
    const __half* weW1t = wh_ptr + 49152;
    const __half* wsW0t = wh_ptr + 65536;
    const __half* wsW1t = wh_ptr + 81920;
    const __half* wdW0t = wh_ptr + 98304;
    const __half* wdW1t = wh_ptr + 131072;

    // 1) convert/transpose weights
    prep_weights<<<576, 256>>>(eW0, eW1, sW0, sW1, dW0, dW1);

    // 2) P1 + P2 + agg-zero, one mega launch
    kernelA<<<NGB + NMB + ZB, NTH, SMEM_BYTES>>>(grid, mesh, weW0t, u_ptr, v_ptr, agg_ptr);

    // 3) edge MLP + scatter  ||  src node MLP (independent, co-scheduled)
    kernelB<<<NEB + NGB, NTH, SMEM_BYTES>>>(
        efeat, grid, src_idx, dst_idx, u_ptr, v_ptr,
        weW0t, eb0, weW1t, eb1, eg, ebt, agg_ptr,
        wsW0t, sb0, wsW1t, sb1, sg, sbt, out_grid);

    // 4) dst node MLP
    kernelC<<<NMB, NTH, SMEM_BYTES>>>(
        agg_ptr, mesh, wdW0t, db0, wdW1t, db1, dg, dbt, out_mesh);
}